// round 16
// baseline (speedup 1.0000x reference)
#include <cuda_runtime.h>
#include <cuda_bf16.h>
#include <cstdint>

#define NB 256
#define NS 2048
#define NK 64
#define LN2F 0.69314718055994531f
#define NBLK 148
#define WPB 8             // 8 warps per block (256 threads), 1 block/SM
#define NWCH 1024         // chain warps: 4 per batch (s=3 stitch)

// Scratch (device globals — no allocation allowed)
__device__ float g_vecA[NB][NK];   // alpha_683 (true fwd)
__device__ float g_vecF[NB][NK];   // f = 1^T M2
__device__ float g_vecG[NB][NK];   // g = M2 1
__device__ float g_vecB[NB][NK];   // beta_1366 (true bwd)
__device__ float g_offA[NB];
__device__ float g_offG[NB];
__device__ float g_offB[NB];
__device__ float g_gold[NB];
__device__ unsigned g_done;        // zero-init; reset by last block each launch

typedef __nv_bfloat162 bf2;

__device__ __forceinline__ bf2 u2b(unsigned u) { return *reinterpret_cast<bf2*>(&u); }
__device__ __forceinline__ unsigned b2u(bf2 v) { return *reinterpret_cast<unsigned*>(&v); }

// Compiler-only ordering fence (loop body is branch-free -> warp convergent;
// MIO executes shared ops in issue order). No WARPSYNC instruction.
#define CFENCE() asm volatile("" ::: "memory")

// matvec, all-bf16: 8x LDS.128 + 64x HFMA2 + 2 HADD2 + 2 PRMT(alu) + 1 HADD2.
// Returns packed (z[2l], z[2l+1]) as bf2.
__device__ __forceinline__ bf2 mv2b(const bf2* __restrict__ s,
                                    const unsigned (&Ee)[32], const unsigned (&Eo)[32]) {
    const uint4* q = (const uint4*)s;
    bf2 zz = __floats2bfloat162_rn(0.f, 0.f);
    bf2 ce0 = zz, ce1 = zz, co0 = zz, co1 = zz;
    #pragma unroll
    for (int g = 0; g < 8; g++) {
        uint4 v = q[g];
        ce0 = __hfma2(u2b(v.x), u2b(Ee[4 * g + 0]), ce0);
        co0 = __hfma2(u2b(v.x), u2b(Eo[4 * g + 0]), co0);
        ce1 = __hfma2(u2b(v.y), u2b(Ee[4 * g + 1]), ce1);
        co1 = __hfma2(u2b(v.y), u2b(Eo[4 * g + 1]), co1);
        ce0 = __hfma2(u2b(v.z), u2b(Ee[4 * g + 2]), ce0);
        co0 = __hfma2(u2b(v.z), u2b(Eo[4 * g + 2]), co0);
        ce1 = __hfma2(u2b(v.w), u2b(Ee[4 * g + 3]), ce1);
        co1 = __hfma2(u2b(v.w), u2b(Eo[4 * g + 3]), co1);
    }
    bf2 ce = __hadd2(ce0, ce1), co = __hadd2(co0, co1);
    // (ce.lo+ce.hi, co.lo+co.hi) via 2 PRMT + 1 HADD2 (PRMT on alu pipe)
    unsigned t1 = __byte_perm(b2u(ce), b2u(co), 0x5410);
    unsigned t2 = __byte_perm(b2u(ce), b2u(co), 0x7632);
    return __hadd2(u2b(t1), u2b(t2));
}

// Exact power-of-two rescale (blocking; used only at chain end), offset in log.
__device__ __forceinline__ void rescale(bf2& v, float& off) {
    bf2 m2 = v;
    #pragma unroll
    for (int d = 16; d; d >>= 1)
        m2 = __hmax2(m2, u2b(__shfl_xor_sync(0xffffffffu, b2u(m2), d)));
    float m = fmaxf(__low2float(m2), __high2float(m2));
    int k = (__float_as_int(m) >> 23) - 127;
    k = k < -120 ? -120 : (k > 120 ? 120 : k);
    float scl = __int_as_float((127 - k) << 23);   // 2^-k (exact in bf16)
    v = __hmul2(v, __floats2bfloat162_rn(scl, scl));
    off += (float)k * LN2F;
}

// Publish warp max of V into mred (5-shfl chain, consumed >=3 steps later).
#define PUB(V) do {                                                     \
    bf2 m2_ = V;                                                        \
    _Pragma("unroll")                                                   \
    for (int d_ = 16; d_; d_ >>= 1)                                     \
        m2_ = __hmax2(m2_, u2b(__shfl_xor_sync(0xffffffffu, b2u(m2_), d_))); \
    mred = fmaxf(__low2float(m2_), __high2float(m2_));                  \
} while (0)

// Apply pending exact power-of-two scale by folding into the exp factors.
#define APPLY() do {                                                    \
    int k_ = ((__float_as_int(mred) >> 23) & 0xff) - 127;               \
    k_ = k_ < -100 ? -100 : (k_ > 120 ? 120 : k_);                      \
    float sf_ = __int_as_float((127 - k_) << 23);                       \
    off += (float)k_ * LN2F;                                            \
    e0_ *= sf_; e1_ *= sf_;                                             \
} while (0)

// ---- forward step: exp early -> matvec(read P) -> hmul -> store P^1 ----
#define FS(P, BUF, AP, PB) do {                                         \
    float2 sv_ = BUF; BUF = *pre; pre += 32;                            \
    float e0_ = __expf(sv_.x), e1_ = __expf(sv_.y);                     \
    if (AP) APPLY();                                                    \
    bf2 e2_ = __floats2bfloat162_rn(e0_, e1_);                          \
    bf2 z_ = mv2b(myd[P], Ee, Eo);                                      \
    av = __hmul2(z_, e2_);                                              \
    if (PB) PUB(av);                                                    \
    myd[P ^ 1][l] = av;                                                 \
    CFENCE();                                                           \
} while (0)

// ---- backward step: w = av*exp -> store P -> matvec(read P) ----
#define BS(P, BUF, AP, PB) do {                                         \
    float2 sv_ = BUF; BUF = *pre; pre -= 32;                            \
    float e0_ = __expf(sv_.x), e1_ = __expf(sv_.y);                     \
    if (AP) APPLY();                                                    \
    bf2 e2_ = __floats2bfloat162_rn(e0_, e1_);                          \
    bf2 w_ = __hmul2(av, e2_);                                          \
    if (PB) PUB(w_);                                                    \
    myd[P][l] = w_;                                                     \
    CFENCE();                                                           \
    av = mv2b(myd[P], Ee, Eo);                                          \
} while (0)

// 148 blocks x 8 warps = 1184 warp slots, 1 block/SM.
//  gid in [0,1024): chain warps — batch = gid>>2, role = gid&3:
//    role0: A    (true fwd,  rows 1..683,     683 steps, seed source+s0, off)
//    role1: f    (fwd ones,  rows 684..1366,  683 steps, off cancels)
//    role2: g    (bwd ones,  rows 1366..684,  683 steps, off)
//    role3: beta (true bwd,  rows 2047..1367, 681 steps, seed sink, off)
//  gid in [1024,1184): gold-path warps (batches strided by 160).
// Last block to finish computes the final loss.
__global__ void __launch_bounds__(32 * WPB, 1)
crf_fused(const float* __restrict__ scores, const int* __restrict__ states,
          const float* __restrict__ trans, const float* __restrict__ source,
          const float* __restrict__ sink, float* __restrict__ out)
{
    __shared__ __align__(16) bf2 vbuf[WPB][2][32];   // [warp][buf][packed pair]
    __shared__ float red[NB];
    __shared__ int s_last;

    const int w = threadIdx.x >> 5;
    const int l = threadIdx.x & 31;
    const int gid = blockIdx.x * WPB + w;

    if (gid >= NWCH) {
        // ---------------- gold path (1-2 batches per warp) ----------------
        for (int b = gid - NWCH; b < NB; b += 160) {
            const int* st = states + b * NS;
            const float* sc = scores + (size_t)b * NS * NK;
            float acc = 0.f;
            #pragma unroll 4
            for (int t = l; t < NS; t += 32) {
                int s = st[t];
                float e = sc[t * NK + s];
                float tr = (t + 1 < NS) ? trans[s * NK + st[t + 1]] : 0.f;
                acc += e + tr;
            }
            #pragma unroll
            for (int d = 16; d; d >>= 1) acc += __shfl_xor_sync(0xffffffffu, acc, d);
            if (l == 0) g_gold[b] = acc + source[st[0]] + sink[st[NS - 1]];
        }
    } else {
        // ---------------- one segment-chain per warp ----------------
        const int b = gid >> 2;
        const int role = gid & 3;
        const bool fwd = role < 2;
        bf2 (*myd)[32] = vbuf[w];

        // E banks: lane's even output column (2l) in Ee, odd (2l+1) in Eo,
        // input index packed in pairs matching the vector layout.
        unsigned Ee[32], Eo[32];
        if (fwd) {
            #pragma unroll
            for (int i2 = 0; i2 < 32; i2++) {
                const float* r0 = trans + (2 * i2) * NK;
                const float* r1 = trans + (2 * i2 + 1) * NK;
                Ee[i2] = b2u(__floats2bfloat162_rn(__expf(r0[2 * l]),     __expf(r1[2 * l])));
                Eo[i2] = b2u(__floats2bfloat162_rn(__expf(r0[2 * l + 1]), __expf(r1[2 * l + 1])));
            }
        } else {
            #pragma unroll
            for (int j2 = 0; j2 < 32; j2++) {
                float2 e0v = ((const float2*)(trans + (2 * l) * NK))[j2];
                float2 e1v = ((const float2*)(trans + (2 * l + 1) * NK))[j2];
                Ee[j2] = b2u(__floats2bfloat162_rn(__expf(e0v.x), __expf(e0v.y)));
                Eo[j2] = b2u(__floats2bfloat162_rn(__expf(e1v.x), __expf(e1v.y)));
            }
        }

        const float2* pre0 = (const float2*)(scores + (size_t)b * NS * NK) + l;
        float off = 0.f, mred = 1.0f;
        bf2 av;

        if (fwd) {
            int base;   // first consumed score row
            if (role == 0) {
                // alpha_0 = exp(source + scores[b,0,:])
                float2 s0 = pre0[0];
                float2 sr = ((const float2*)source)[l];
                av = __floats2bfloat162_rn(__expf(sr.x + s0.x), __expf(sr.y + s0.y));
                base = 1;
            } else {
                av = __floats2bfloat162_rn(1.f, 1.f);
                base = 684;
            }
            PUB(av);
            myd[0][l] = av;
            __syncwarp();   // one-time init sync

            // depth-8 prefetch ring
            float2 f0 = pre0[(base + 0) * 32], f1 = pre0[(base + 1) * 32];
            float2 f2 = pre0[(base + 2) * 32], f3 = pre0[(base + 3) * 32];
            float2 f4 = pre0[(base + 4) * 32], f5 = pre0[(base + 5) * 32];
            float2 f6 = pre0[(base + 6) * 32], f7 = pre0[(base + 7) * 32];
            const float2* pre = pre0 + (base + 8) * 32;

            // 85 groups of 8 + 3 tail = 683 steps (prefetch <= base+690 <= 1374)
            // Apply pending scale at step 0; publish next at step 5.
            #pragma unroll 1
            for (int grp = 0; grp < 85; grp++) {
                FS(0, f0, 1, 0); FS(1, f1, 0, 0); FS(0, f2, 0, 0); FS(1, f3, 0, 0);
                FS(0, f4, 0, 0); FS(1, f5, 0, 1); FS(0, f6, 0, 0); FS(1, f7, 0, 0);
            }
            FS(0, f0, 1, 0); FS(1, f1, 0, 0); FS(0, f2, 0, 0);

            rescale(av, off);   // final peg
            float* dst = (role == 0) ? g_vecA[b] : g_vecF[b];
            dst[2 * l]     = __low2float(av);
            dst[2 * l + 1] = __high2float(av);
            if (l == 0 && role == 0) g_offA[b] = off;   // f's offset cancels
        } else {
            int base;   // first consumed score row (descending)
            if (role == 2) {
                av = __floats2bfloat162_rn(1.f, 1.f);
                base = 1366;
            } else {
                float2 sk = ((const float2*)sink)[l];
                av = __floats2bfloat162_rn(__expf(sk.x), __expf(sk.y));
                base = 2047;
            }
            PUB(av);

            // depth-8 prefetch ring (descending)
            float2 f0 = pre0[(base - 0) * 32], f1 = pre0[(base - 1) * 32];
            float2 f2 = pre0[(base - 2) * 32], f3 = pre0[(base - 3) * 32];
            float2 f4 = pre0[(base - 4) * 32], f5 = pre0[(base - 5) * 32];
            float2 f6 = pre0[(base - 6) * 32], f7 = pre0[(base - 7) * 32];
            const float2* pre = pre0 + (base - 8) * 32;

            // role2: 85x8+3 = 683 steps (rows 1366..684);
            // role3: 85x8+1 = 681 steps (rows 2047..1367).
            // Prefetch >= base-690 >= 676, in bounds.
            #pragma unroll 1
            for (int grp = 0; grp < 85; grp++) {
                BS(0, f0, 1, 0); BS(1, f1, 0, 0); BS(0, f2, 0, 0); BS(1, f3, 0, 0);
                BS(0, f4, 0, 0); BS(1, f5, 0, 1); BS(0, f6, 0, 0); BS(1, f7, 0, 0);
            }
            BS(0, f0, 1, 0);
            if (role == 2) { BS(1, f1, 0, 0); BS(0, f2, 0, 0); }

            rescale(av, off);   // final peg
            float* dst = (role == 2) ? g_vecG[b] : g_vecB[b];
            dst[2 * l]     = __low2float(av);
            dst[2 * l + 1] = __high2float(av);
            if (l == 0) {
                if (role == 2) g_offG[b] = off; else g_offB[b] = off;
            }
        }
    }

    // ---------------- completion: last block reduces ----------------
    __syncthreads();
    if (threadIdx.x == 0) {
        __threadfence();
        s_last = (atomicAdd(&g_done, 1u) == NBLK - 1u) ? 1 : 0;
    }
    __syncthreads();
    if (!s_last) return;
    __threadfence();

    // loss_b = log(A.g) + log(f.beta) - log(f.1) + offA + offG + offB - gold
    if (threadIdx.x < NB) {
        const int b = threadIdx.x;
        float dAG = 0.f, dFB = 0.f, dF1 = 0.f;
        #pragma unroll 4
        for (int j = 0; j < NK; j++) {
            float fj = g_vecF[b][j];
            dAG += g_vecA[b][j] * g_vecG[b][j];
            dFB += fj * g_vecB[b][j];
            dF1 += fj;
        }
        red[b] = logf(dAG) + logf(dFB) - logf(dF1)
               + g_offA[b] + g_offG[b] + g_offB[b] - g_gold[b];
    }
    __syncthreads();
    if (threadIdx.x < 32) {
        float s = 0.f;
        for (int i = threadIdx.x; i < NB; i += 32) s += red[i];
        #pragma unroll
        for (int d = 16; d; d >>= 1) s += __shfl_xor_sync(0xffffffffu, s, d);
        if (threadIdx.x == 0) { out[0] = s * (1.0f / NB); g_done = 0; }
    }
}

extern "C" void kernel_launch(void* const* d_in, const int* in_sizes, int n_in,
                              void* d_out, int out_size)
{
    const float* scores = (const float*)d_in[0];
    const int*   states = (const int*)d_in[1];
    const float* trans  = (const float*)d_in[2];
    const float* source = (const float*)d_in[3];
    const float* sink   = (const float*)d_in[4];

    crf_fused<<<NBLK, 32 * WPB>>>(scores, states, trans, source, sink, (float*)d_out);
}